// round 11
// baseline (speedup 1.0000x reference)
#include <cuda_runtime.h>
#include <cuda_fp16.h>
#include <cstdint>

#define D       64
#define HW      4096
#define KCODES  1024

// codebook pre-scale 2^10 (exact); dot scale-back 2^-10 (exact)
#define ESCALE   1024.0f
#define EINV     0.0009765625f

// ---------------- device scratch (no allocation allowed) -------------------
// B fragments: [half(2)][ntile(64)][kstep(4)][lane(32)] x uint4 {bh0,bh1,bl0,bl1}
__device__ __half g_E[KCODES * D * 2];   // 256KB
__device__ float  g_sse[KCODES];

// pack two floats to fp16x2 (x0 -> low half)
__device__ __forceinline__ uint32_t packh(float x0, float x1) {
    uint32_t r;
    asm("cvt.rn.f16x2.f32 %0, %1, %2;" : "=r"(r) : "f"(x1), "f"(x0));
    return r;
}

// C += A(f16 16x16) * B(f16 16x8), fp32 accumulate.
__device__ __forceinline__ void mma_f16(float c[4], const uint32_t* a,
                                        uint32_t b0, uint32_t b1) {
    asm("mma.sync.aligned.m16n8k16.row.col.f32.f16.f16.f32 "
        "{%0,%1,%2,%3}, {%4,%5,%6,%7}, {%8,%9}, {%0,%1,%2,%3};"
        : "+f"(c[0]), "+f"(c[1]), "+f"(c[2]), "+f"(c[3])
        : "r"(a[0]), "r"(a[1]), "r"(a[2]), "r"(a[3]), "r"(b0), "r"(b1));
}

// ---------------- prep: codebook -> f16 hi/lo B-fragments (scaled) + sse ---
// m16n8k16 .col B-frag: b0 holds k={2*cb4, 2*cb4+1}, b1 holds k+8, col n = lane>>2.
__global__ void vq_prep(const float* __restrict__ cb) {
    int id = blockIdx.x * blockDim.x + threadIdx.x;   // 65536 = 1024*64
    int n = id >> 6, k = id & 63;
    float es = cb[id] * ESCALE;                 // exact power-of-2 scale
    __half hi = __float2half(es);
    __half lo = __float2half(es - __half2float(hi));
    int ntile = n >> 3, nrow = n & 7;
    int kstep = k >> 4, kin = k & 15;
    int j    = kin >> 3;          // reg index (b0/b1)
    int cb4  = (kin & 7) >> 1;
    int elem = k & 1;
    int slot = (ntile * 4 + kstep) * 32 + nrow * 4 + cb4;   // 16B slots
    g_E[slot * 8 + j * 2 + elem]     = hi;
    g_E[slot * 8 + 4 + j * 2 + elem] = lo;
    if (k == 0) {   // sequential row sum, unscaled — same order as passing kernels
        const float* r = cb + n * D;
        float s = 0.0f;
        for (int d0 = 0; d0 < D; ++d0) s += r[d0] * r[d0];
        g_sse[n] = s;
    }
}

#define SMEM_REQ (131072 + 4096)
#define THREADS  512

// ---------------- main: 3xFP16 GEMM + argmin over ALL codes + output -------
__global__ void __launch_bounds__(THREADS, 1)
vq_main(const float* __restrict__ input, const float* __restrict__ cb,
        float* __restrict__ out) {
    extern __shared__ char smraw[];
    uint4* sB   = (uint4*)smraw;                 // 8192 slots = 128KB (one half)
    float* sSse = (float*)(smraw + 131072);      // 1024 floats

    const int tid  = threadIdx.x;
    const int w    = tid >> 5;    // 0..15
    const int lane = tid & 31;
    const int grp  = lane >> 2;   // 0..7
    const int cb4  = lane & 3;    // 0..3

    // stage sse once (visibility covered by the first staging __syncthreads)
    #pragma unroll
    for (int i = 0; i < 2; ++i) sSse[tid + i * THREADS] = g_sse[tid + i * THREADS];

    #pragma unroll 1
    for (int p = 0; p < 2; ++p) {
        // one 16-token m-tile per warp per p-iter
        const int base = blockIdx.x * 512 + p * 256 + w * 16;

        // ---- A fragment: 16 tokens, fp16 hi/lo planes ----
        uint32_t Ahi[16], Alo[16];
        float ssx0, ssx1;
        {
            const int row0 = base + grp;
            const int b    = row0 >> 12;
            const int hw   = row0 & (HW - 1);
            const float* p0 = input + (size_t)b * D * HW + hw;
            const float* p1 = p0 + 8;
            float s0 = 0.0f, s1 = 0.0f;
            #pragma unroll
            for (int ks = 0; ks < 4; ++ks) {
                const int k0 = ks * 16 + 2 * cb4;
                float xa, xb;
                // a0: row grp, k={k0,k0+1}
                xa = p0[(size_t)k0 * HW];        xb = p0[(size_t)(k0 + 1) * HW];
                s0 = fmaf(xa, xa, s0);           s0 = fmaf(xb, xb, s0);
                {
                    uint32_t h = packh(xa, xb);
                    __half2 h2 = *(__half2*)&h;
                    Ahi[ks * 4 + 0] = h;
                    Alo[ks * 4 + 0] = packh(xa - __half2float(__low2half(h2)),
                                            xb - __half2float(__high2half(h2)));
                }
                // a1: row grp+8, k={k0,k0+1}
                xa = p1[(size_t)k0 * HW];        xb = p1[(size_t)(k0 + 1) * HW];
                s1 = fmaf(xa, xa, s1);           s1 = fmaf(xb, xb, s1);
                {
                    uint32_t h = packh(xa, xb);
                    __half2 h2 = *(__half2*)&h;
                    Ahi[ks * 4 + 1] = h;
                    Alo[ks * 4 + 1] = packh(xa - __half2float(__low2half(h2)),
                                            xb - __half2float(__high2half(h2)));
                }
                // a2: row grp, k={k0+8,k0+9}
                xa = p0[(size_t)(k0 + 8) * HW];  xb = p0[(size_t)(k0 + 9) * HW];
                s0 = fmaf(xa, xa, s0);           s0 = fmaf(xb, xb, s0);
                {
                    uint32_t h = packh(xa, xb);
                    __half2 h2 = *(__half2*)&h;
                    Ahi[ks * 4 + 2] = h;
                    Alo[ks * 4 + 2] = packh(xa - __half2float(__low2half(h2)),
                                            xb - __half2float(__high2half(h2)));
                }
                // a3: row grp+8, k={k0+8,k0+9}
                xa = p1[(size_t)(k0 + 8) * HW];  xb = p1[(size_t)(k0 + 9) * HW];
                s1 = fmaf(xa, xa, s1);           s1 = fmaf(xb, xb, s1);
                {
                    uint32_t h = packh(xa, xb);
                    __half2 h2 = *(__half2*)&h;
                    Ahi[ks * 4 + 3] = h;
                    Alo[ks * 4 + 3] = packh(xa - __half2float(__low2half(h2)),
                                            xb - __half2float(__high2half(h2)));
                }
            }
            // ssx: common-mode per token — sum the 4 cb4 lanes
            s0 += __shfl_xor_sync(0xffffffffu, s0, 1);
            s0 += __shfl_xor_sync(0xffffffffu, s0, 2);
            s1 += __shfl_xor_sync(0xffffffffu, s1, 1);
            s1 += __shfl_xor_sync(0xffffffffu, s1, 2);
            ssx0 = s0;
            ssx1 = s1;
        }

        float best[2] = {3.4e38f, 3.4e38f};
        int   bidx[2] = {0, 0};

        #pragma unroll 1
        for (int half = 0; half < 2; ++half) {
            __syncthreads();    // previous half (or prior p) consumers done
            // stage 512 codes' fragments (128KB), coalesced uint4
            const uint4* src = ((const uint4*)g_E) + half * 8192;
            #pragma unroll
            for (int i = 0; i < 16; ++i)
                sB[tid + i * THREADS] = src[tid + i * THREADS];
            __syncthreads();

            #pragma unroll 1
            for (int ng = 0; ng < 64; ng += 2) {
                float Chh[2][4], Cx[2][4];
                #pragma unroll
                for (int u = 0; u < 2; ++u)
                    #pragma unroll
                    for (int v = 0; v < 4; ++v) {
                        Chh[u][v] = 0.0f;
                        Cx[u][v]  = 0.0f;
                    }

                #pragma unroll
                for (int ks = 0; ks < 4; ++ks) {
                    #pragma unroll
                    for (int u = 0; u < 2; ++u) {
                        uint4 B = sB[((ng + u) * 4 + ks) * 32 + lane];
                        mma_f16(Chh[u], &Ahi[ks * 4], B.x, B.y); // hi*hi
                        mma_f16(Cx[u],  &Ahi[ks * 4], B.z, B.w); // hi*lo
                        mma_f16(Cx[u],  &Alo[ks * 4], B.x, B.y); // lo*hi
                    }
                }

                #pragma unroll
                for (int u = 0; u < 2; ++u) {
                    const int kg = half * 512 + (ng + u) * 8 + 2 * cb4;
                    float2 ss = *(const float2*)&sSse[kg];
                    // scale-back by 2^-10 is exact
                    float c0 = (Chh[u][0] + Cx[u][0]) * EINV;
                    float c1 = (Chh[u][1] + Cx[u][1]) * EINV;
                    float c2 = (Chh[u][2] + Cx[u][2]) * EINV;
                    float c3 = (Chh[u][3] + Cx[u][3]) * EINV;
                    float d00 = (ssx0 + ss.x) - 2.0f * c0;
                    float d01 = (ssx0 + ss.y) - 2.0f * c1;
                    float d10 = (ssx1 + ss.x) - 2.0f * c2;
                    float d11 = (ssx1 + ss.y) - 2.0f * c3;
                    if (d00 < best[0]) { best[0] = d00; bidx[0] = kg;     }
                    if (d01 < best[0]) { best[0] = d01; bidx[0] = kg + 1; }
                    if (d10 < best[1]) { best[1] = d10; bidx[1] = kg;     }
                    if (d11 < best[1]) { best[1] = d11; bidx[1] = kg + 1; }
                }
            }
        }

        // reduce over the 4 cb4 lanes; ties -> lower index (global first-min)
        #pragma unroll
        for (int h = 0; h < 2; ++h)
            #pragma unroll
            for (int o = 1; o <= 2; o <<= 1) {
                float od = __shfl_xor_sync(0xffffffffu, best[h], o);
                int   oi = __shfl_xor_sync(0xffffffffu, bidx[h], o);
                if (od < best[h] || (od == best[h] && oi < bidx[h])) {
                    best[h] = od; bidx[h] = oi;
                }
            }

        // lanes cb4==0 and cb4==1 each write one token: h = cb4
        if (cb4 < 2) {
            const int row = base + grp + cb4 * 8;
            const int b   = row >> 12;
            const int hw  = row & (HW - 1);
            const int bi  = bidx[cb4];
            const float4* e  = (const float4*)cb + bi * (D / 4);
            float*        op = out + (size_t)b * D * HW + hw;
            #pragma unroll
            for (int j = 0; j < D / 4; ++j) {
                float4 v = __ldg(e + j);
                op[(size_t)(4 * j + 0) * HW] = v.x;
                op[(size_t)(4 * j + 1) * HW] = v.y;
                op[(size_t)(4 * j + 2) * HW] = v.z;
                op[(size_t)(4 * j + 3) * HW] = v.w;
            }
        }
    }
}

extern "C" void kernel_launch(void* const* d_in, const int* in_sizes, int n_in,
                              void* d_out, int out_size) {
    const float* input    = (const float*)d_in[0];   // [16, 64, 64, 64] fp32 NCHW
    const float* codebook = (const float*)d_in[1];   // [1024, 64] fp32
    float*       out      = (float*)d_out;

    cudaFuncSetAttribute(vq_main, cudaFuncAttributeMaxDynamicSharedMemorySize, SMEM_REQ);
    vq_prep<<<64, 1024>>>(codebook);
    vq_main<<<128, THREADS, SMEM_REQ>>>(input, codebook, out);
}